// round 14
// baseline (speedup 1.0000x reference)
#include <cuda_runtime.h>

#define BSZ 256
#define HSZ 512
#define NSZ 16
#define TSTEPS 63
#define ODIM 9
#define CLSZ 16
#define NBLK 128
#define NTHR 1024

typedef unsigned long long ull;

__device__ __forceinline__ ull pack2(float lo, float hi) {
    ull r; asm("mov.b64 %0,{%1,%2};" : "=l"(r) : "f"(lo), "f"(hi)); return r;
}
__device__ __forceinline__ float2 unpack2(ull v) {
    float2 r; asm("mov.b64 {%0,%1},%2;" : "=f"(r.x), "=f"(r.y) : "l"(v)); return r;
}
__device__ __forceinline__ ull fma2v(ull a, ull b, ull c) {
    ull d; asm("fma.rn.f32x2 %0,%1,%2,%3;" : "=l"(d) : "l"(a), "l"(b), "l"(c)); return d;
}
__device__ __forceinline__ float gelu_exact(float x) {
    return 0.5f * x * (1.0f + erff(x * 0.70710678118654752440f));
}
__device__ __forceinline__ float sigm(float x) {
    return 1.0f / (1.0f + expf(-x));
}

#define CLUSTER_SYNC() do { \
    asm volatile("barrier.cluster.arrive.aligned;" ::: "memory"); \
    asm volatile("barrier.cluster.wait.aligned;" ::: "memory"); \
} while (0)

// ---------- global scratch ----------
__device__ __align__(16) float g_enc[BSZ * 6 * HSZ];
__device__ __align__(16) float g_gact[BSZ * HSZ];
__device__ __align__(16) float g_part[NBLK * 32 * HSZ];     // [cl*16+kc][32 rows][512]
__device__ __align__(16) float g_states[2 * BSZ * HSZ * NSZ];

// dynamic smem: Ws0[32][512] | Ws1[32][512] | As[32][36]
#define WS_FLOATS (32 * HSZ)
#define AS_OFF (2 * WS_FLOATS)
#define SMEM_FLOATS (2 * WS_FLOATS + 32 * 36)
#define SMEM_BYTES (SMEM_FLOATS * 4)

// ============================================================
__global__ void k_enc(const float* __restrict__ inseq,
                      const float* __restrict__ inW,
                      const float* __restrict__ inb) {
    int idx = blockIdx.x * 256 + threadIdx.x;   // < B*6*H
    int h = idx & (HSZ - 1);
    int bs = idx >> 9;
    int b = bs / 6, s = bs - b * 6;
    const float* r = inseq + (b * 64 + s) * 3;
    g_enc[idx] = fmaf(r[0], inW[h],
                 fmaf(r[1], inW[HSZ + h],
                 fmaf(r[2], inW[2 * HSZ + h], inb[h])));
}

// ============================================================
// GEMM phase: cluster-local split-K-16.
// CTA kc: k in [32kc, 32kc+32), rows [R0, R0+32), all 512 cols.
// Thread tile 4 rows x 4 cols (8 rgroups x 128 cgroups), row-pair f32x2.
// ============================================================
__device__ __forceinline__ void g_phase(const float* __restrict__ Wsm,
                                        float* __restrict__ As,
                                        int R0, int kc, int rg, int cg,
                                        float* __restrict__ Pdst) {
    int t = threadIdx.x;
    // stage A: 32 rows x 32 k transposed. lanes read 32 consecutive k -> coalesced.
    {
        int row = t >> 5, kl = t & 31;
        As[kl * 36 + row] = __ldcg(&g_gact[(R0 + row) * HSZ + 32 * kc + kl]);
    }
    __syncthreads();

    int rbase = rg * 4, cb = cg * 4;
    ull acc[2][4];
#pragma unroll
    for (int i = 0; i < 2; i++)
#pragma unroll
        for (int j = 0; j < 4; j++) acc[i][j] = 0ULL;

#pragma unroll
    for (int k = 0; k < 32; k++) {
        ulonglong2 u = *(const ulonglong2*)&As[k * 36 + rbase];  // rows (0,1),(2,3)
        float4 wv = *(const float4*)&Wsm[k * HSZ + cb];
        ull b0 = pack2(wv.x, wv.x), b1 = pack2(wv.y, wv.y);
        ull b2 = pack2(wv.z, wv.z), b3 = pack2(wv.w, wv.w);
        acc[0][0] = fma2v(u.x, b0, acc[0][0]); acc[0][1] = fma2v(u.x, b1, acc[0][1]);
        acc[0][2] = fma2v(u.x, b2, acc[0][2]); acc[0][3] = fma2v(u.x, b3, acc[0][3]);
        acc[1][0] = fma2v(u.y, b0, acc[1][0]); acc[1][1] = fma2v(u.y, b1, acc[1][1]);
        acc[1][2] = fma2v(u.y, b2, acc[1][2]); acc[1][3] = fma2v(u.y, b3, acc[1][3]);
    }

#pragma unroll
    for (int rp = 0; rp < 2; rp++) {
        float2 v0 = unpack2(acc[rp][0]), v1 = unpack2(acc[rp][1]);
        float2 v2 = unpack2(acc[rp][2]), v3 = unpack2(acc[rp][3]);
        int r_even = rbase + rp * 2;
        *(float4*)&Pdst[(size_t)(r_even) * HSZ + cb]     = make_float4(v0.x, v1.x, v2.x, v3.x);
        *(float4*)&Pdst[(size_t)(r_even + 1) * HSZ + cb] = make_float4(v0.y, v1.y, v2.y, v3.y);
    }
    __syncthreads();   // As free for reuse
}

// ============================================================
// persistent cluster decode kernel
// ============================================================
extern "C" __global__ void __launch_bounds__(NTHR, 1) __cluster_dims__(CLSZ, 1, 1)
k_persist(const float* __restrict__ inW, const float* __restrict__ inb,
          const float* __restrict__ A, const float* __restrict__ Bm,
          const float* __restrict__ Cm, const float* __restrict__ D,
          const float* __restrict__ oW, const float* __restrict__ ob,
          const float* __restrict__ lng, const float* __restrict__ lnb,
          const float* __restrict__ hW, const float* __restrict__ hb,
          float* __restrict__ out) {
    extern __shared__ float smf[];
    float* Ws0 = smf;
    float* Ws1 = smf + WS_FLOATS;
    float* As = smf + AS_OFF;        // staging; reused as xdc[2][512] in HEAD

    __shared__ float red_s[32], redq_s[32];
    __shared__ float stat_s[4];
    __shared__ float s_gv[2][12];
    __shared__ float s_dv[2][3];
    __shared__ int s_ptr[2];

    int t = threadIdx.x, bid = blockIdx.x;
    int cl = bid >> 4, kc = bid & 15;
    int lane = t & 31, ww = t >> 5;
    int bb = t >> 9, h = t & 511;
    int R0 = cl * 32;
    int myrow = R0 + 2 * kc + bb;
    int rg = t >> 7, cg = t & 127;

    const float* A1p = A + HSZ * NSZ;  const float* B1p = Bm + HSZ * NSZ;
    const float* C1p = Cm + HSZ * NSZ; const float* D1p = D + HSZ;
    const float* lng1 = lng + HSZ;     const float* lnb1 = lnb + HSZ;
    const float* ob1 = ob + HSZ;

    float* Pme = g_part + (size_t)bid * 32 * HSZ;

    // ---- stage W slice (both layers) once; coalesced float4 ----
    {
        const size_t HH = (size_t)HSZ * HSZ;
#pragma unroll
        for (int i = 0; i < 8; i++) {
            int fidx = t + i * NTHR;               // 0..8191 float4s
            int l = fidx >> 12, rem = fidx & 4095;
            int k = rem >> 7, c4 = rem & 127;
            float4 v = __ldg((const float4*)&oW[l * HH + (size_t)(32 * kc + k) * HSZ + c4 * 4]);
            *(float4*)&smf[l * WS_FLOATS + k * HSZ + c4 * 4] = v;
        }
    }

    float ctx = 0.0f;

    // ---- initial S0: dec=[0,0,1], layer-0 states written (not read) ----
    {
        float x = __ldg(&inW[2 * HSZ + h]) + __ldg(&inb[h]);
        float acc = 0.0f;
        float4* sp = (float4*)&g_states[((size_t)myrow * HSZ + h) * NSZ];
#pragma unroll
        for (int q = 0; q < 4; q++) {
            float4 cb4 = __ldg((const float4*)(Bm + h * NSZ + q * 4));
            float4 cc4 = __ldg((const float4*)(Cm + h * NSZ + q * 4));
            float4 sv = make_float4(cb4.x * x, cb4.y * x, cb4.z * x, cb4.w * x);
            sp[q] = sv;
            acc += cc4.x * sv.x + cc4.y * sv.y + cc4.z * sv.z + cc4.w * sv.w;
        }
        __stcg(&g_gact[myrow * HSZ + h], gelu_exact(fmaf(__ldg(&D[h]), x, acc)));
    }
    CLUSTER_SYNC();

    for (int i = 0; i < TSTEPS; i++) {
        int s0f = (i == 0) ? 1 : 0;

        // ---------- G0 ----------
        g_phase(Ws0, As, R0, kc, rg, cg, Pme);
        CLUSTER_SYNC();

        // ---------- S1: partials -> z0, LN0, layer-1 SSM -> gact ----------
        {
            float y = 0.0f;
#pragma unroll
            for (int j = 0; j < 16; j++)
                y += __ldcg(&g_part[((size_t)(cl * 16 + j) * 32 + 2 * kc + bb) * HSZ + h]);
            y += __ldg(&ob[h]);
            float zz = s0f ? (y + __ldg(&inW[2 * HSZ + h]) + __ldg(&inb[h])) : 2.0f * y;

            float s = zz, q = zz * zz;
#pragma unroll
            for (int d = 16; d; d >>= 1) {
                s += __shfl_xor_sync(0xFFFFFFFFu, s, d);
                q += __shfl_xor_sync(0xFFFFFFFFu, q, d);
            }
            if (lane == 0) { red_s[ww] = s; redq_s[ww] = q; }
            __syncthreads();
            if (t == 0) {
#pragma unroll
                for (int hf = 0; hf < 2; hf++) {
                    float ss = 0.0f, qq = 0.0f;
#pragma unroll
                    for (int k = 0; k < 16; k++) { ss += red_s[hf * 16 + k]; qq += redq_s[hf * 16 + k]; }
                    float m = ss * (1.0f / HSZ);
                    stat_s[hf * 2] = m;
                    stat_s[hf * 2 + 1] = rsqrtf(qq * (1.0f / HSZ) - m * m + 1e-5f);
                }
            }
            __syncthreads();
            float x = (zz - stat_s[bb * 2]) * stat_s[bb * 2 + 1] * __ldg(&lng[h]) + __ldg(&lnb[h]);

            float acc = 0.0f;
            float4* sp = (float4*)&g_states[(((size_t)BSZ + myrow) * HSZ + h) * NSZ];
#pragma unroll
            for (int q4 = 0; q4 < 4; q4++) {
                float4 ca  = __ldg((const float4*)(A1p + h * NSZ + q4 * 4));
                float4 cb4 = __ldg((const float4*)(B1p + h * NSZ + q4 * 4));
                float4 cc4 = __ldg((const float4*)(C1p + h * NSZ + q4 * 4));
                float4 sv;
                if (s0f) {
                    sv = make_float4(cb4.x * x, cb4.y * x, cb4.z * x, cb4.w * x);
                } else {
                    sv = sp[q4];
                    sv.x = fmaf(ca.x, sv.x, cb4.x * x); sv.y = fmaf(ca.y, sv.y, cb4.y * x);
                    sv.z = fmaf(ca.z, sv.z, cb4.z * x); sv.w = fmaf(ca.w, sv.w, cb4.w * x);
                }
                sp[q4] = sv;
                acc += cc4.x * sv.x + cc4.y * sv.y + cc4.z * sv.z + cc4.w * sv.w;
            }
            __stcg(&g_gact[myrow * HSZ + h], gelu_exact(fmaf(__ldg(&D1p[h]), x, acc)));
        }
        CLUSTER_SYNC();

        // ---------- G1 ----------
        g_phase(Ws1, As, R0, kc, rg, cg, Pme);
        CLUSTER_SYNC();

        // ---------- HEAD + fused next-step S0 (CTA-local rows) ----------
        {
            float y = 0.0f;
#pragma unroll
            for (int j = 0; j < 16; j++)
                y += __ldcg(&g_part[((size_t)(cl * 16 + j) * 32 + 2 * kc + bb) * HSZ + h]);
            y += __ldg(&ob1[h]);
            float zz = s0f ? (y + __ldg(&inW[2 * HSZ + h]) + __ldg(&inb[h])) : 2.0f * y;

            float s = zz, q = zz * zz;
#pragma unroll
            for (int d = 16; d; d >>= 1) {
                s += __shfl_xor_sync(0xFFFFFFFFu, s, d);
                q += __shfl_xor_sync(0xFFFFFFFFu, q, d);
            }
            if (lane == 0) { red_s[ww] = s; redq_s[ww] = q; }
            __syncthreads();
            if (t == 0) {
#pragma unroll
                for (int hf = 0; hf < 2; hf++) {
                    float ss = 0.0f, qq = 0.0f;
#pragma unroll
                    for (int k = 0; k < 16; k++) { ss += red_s[hf * 16 + k]; qq += redq_s[hf * 16 + k]; }
                    float m = ss * (1.0f / HSZ);
                    stat_s[hf * 2] = m;
                    stat_s[hf * 2 + 1] = rsqrtf(qq * (1.0f / HSZ) - m * m + 1e-5f);
                }
            }
            __syncthreads();
            float xd = (zz - stat_s[bb * 2]) * stat_s[bb * 2 + 1] * __ldg(&lng1[h]) + __ldg(&lnb1[h]);
            float* xdc = As;
            xdc[bb * 512 + h] = xd + ctx;
            __syncthreads();

            int half = ww >> 4, wl = ww & 15;
            if (wl < ODIM) {
                float a = 0.0f;
#pragma unroll
                for (int q2 = 0; q2 < 16; q2++) {
                    int k = q2 * 32 + lane;
                    a = fmaf(xdc[half * 512 + k], __ldg(&hW[k * ODIM + wl]), a);
                }
#pragma unroll
                for (int d = 16; d; d >>= 1) a += __shfl_xor_sync(0xFFFFFFFFu, a, d);
                if (lane == 0) s_gv[half][wl] = a + __ldg(&hb[wl]);
            }
            __syncthreads();

            int lt = t & 511;
            bool is_out = ((i & 1) == 0);
            if (is_out) {
                if (lt < ODIM) out[(size_t)myrow * (TSTEPS * ODIM) + i * ODIM + lt] = sigm(s_gv[bb][lt]);
                if (lt == 0) {
                    s_dv[bb][0] = (sigm(s_gv[bb][0]) > 0.5f) ? 1.0f : 0.0f;
                    s_dv[bb][1] = 1.0f; s_dv[bb][2] = 0.0f;
                }
            } else {
                if (lt == 0) {
                    float best = sigm(s_gv[bb][3]); int p = 0;
#pragma unroll
                    for (int c = 1; c < 6; c++) {
                        float v = sigm(s_gv[bb][3 + c]);
                        if (v > best) { best = v; p = c; }
                    }
                    s_ptr[bb] = p;
                    s_dv[bb][0] = 0.0f; s_dv[bb][1] = 0.0f; s_dv[bb][2] = 1.0f;
                }
                __syncthreads();               // uniform branch (step parity)
                ctx += __ldg(&g_enc[((size_t)myrow * 6 + s_ptr[bb]) * HSZ + h]);
                if (wl < ODIM) {
                    int rr = R0 + 2 * kc + half;
                    const float* ev = g_enc + ((size_t)rr * 6 + s_ptr[half]) * HSZ;
                    float a2 = 0.0f;
#pragma unroll
                    for (int q2 = 0; q2 < 16; q2++) {
                        int k = q2 * 32 + lane;
                        a2 = fmaf(__ldg(&ev[k]), __ldg(&hW[k * ODIM + wl]), a2);
                    }
#pragma unroll
                    for (int d = 16; d; d >>= 1) a2 += __shfl_xor_sync(0xFFFFFFFFu, a2, d);
                    if (lane == 0)
                        out[(size_t)rr * (TSTEPS * ODIM) + i * ODIM + wl] = sigm(s_gv[half][wl] + a2);
                }
            }
            __syncthreads();

            if (i == TSTEPS - 1) break;

            // fused next-step S0 (dec in s_dv, block-local)
            float d0 = s_dv[bb][0], d1 = s_dv[bb][1], d2 = s_dv[bb][2];
            float x = fmaf(d0, __ldg(&inW[h]),
                      fmaf(d1, __ldg(&inW[HSZ + h]),
                      fmaf(d2, __ldg(&inW[2 * HSZ + h]), __ldg(&inb[h]))));
            float acc = 0.0f;
            float4* sp = (float4*)&g_states[((size_t)myrow * HSZ + h) * NSZ];
#pragma unroll
            for (int q4 = 0; q4 < 4; q4++) {
                float4 ca  = __ldg((const float4*)(A + h * NSZ + q4 * 4));
                float4 cb4 = __ldg((const float4*)(Bm + h * NSZ + q4 * 4));
                float4 cc4 = __ldg((const float4*)(Cm + h * NSZ + q4 * 4));
                float4 sv = sp[q4];
                sv.x = fmaf(ca.x, sv.x, cb4.x * x); sv.y = fmaf(ca.y, sv.y, cb4.y * x);
                sv.z = fmaf(ca.z, sv.z, cb4.z * x); sv.w = fmaf(ca.w, sv.w, cb4.w * x);
                sp[q4] = sv;
                acc += cc4.x * sv.x + cc4.y * sv.y + cc4.z * sv.z + cc4.w * sv.w;
            }
            __stcg(&g_gact[myrow * HSZ + h], gelu_exact(fmaf(__ldg(&D[h]), x, acc)));
        }
        CLUSTER_SYNC();
    }
}

// ============================================================
// Launch: 2 graph nodes
// ============================================================
extern "C" void kernel_launch(void* const* d_in, const int* in_sizes, int n_in,
                              void* d_out, int out_size) {
    int o = (n_in >= 14) ? 1 : 0;
    const float* inseq = (const float*)d_in[0];
    const float* inW = (const float*)d_in[1 + o];
    const float* inb = (const float*)d_in[2 + o];
    const float* A   = (const float*)d_in[3 + o];
    const float* Bm  = (const float*)d_in[4 + o];
    const float* Cm  = (const float*)d_in[5 + o];
    const float* D   = (const float*)d_in[6 + o];
    const float* oW  = (const float*)d_in[7 + o];
    const float* ob  = (const float*)d_in[8 + o];
    const float* lng = (const float*)d_in[9 + o];
    const float* lnb = (const float*)d_in[10 + o];
    const float* hW  = (const float*)d_in[11 + o];
    const float* hb  = (const float*)d_in[12 + o];
    float* out = (float*)d_out;

    cudaFuncSetAttribute(k_persist, cudaFuncAttributeNonPortableClusterSizeAllowed, 1);
    cudaFuncSetAttribute(k_persist, cudaFuncAttributeMaxDynamicSharedMemorySize, SMEM_BYTES);

    k_enc<<<(BSZ * 6 * HSZ) / 256, 256>>>(inseq, inW, inb);
    k_persist<<<NBLK, NTHR, SMEM_BYTES>>>(inW, inb, A, Bm, Cm, D,
                                          oW, ob, lng, lnb, hW, hb, out);
}

// round 15
// speedup vs baseline: 1.5719x; 1.5719x over previous
#include <cuda_runtime.h>

#define BSZ 256
#define HSZ 512
#define NSZ 16
#define TSTEPS 63
#define ODIM 9
#define KC 8            // split-K chunks
#define KCH 64          // K per chunk

typedef unsigned long long ull;

// ---------- packed f32x2 helpers (sm_103a FFMA2 path, PTX-only) ----------
__device__ __forceinline__ ull pack2(float lo, float hi) {
    ull r; asm("mov.b64 %0,{%1,%2};" : "=l"(r) : "f"(lo), "f"(hi)); return r;
}
__device__ __forceinline__ float2 unpack2(ull v) {
    float2 r; asm("mov.b64 {%0,%1},%2;" : "=f"(r.x), "=f"(r.y) : "l"(v)); return r;
}
__device__ __forceinline__ ull fma2v(ull a, ull b, ull c) {
    ull d; asm("fma.rn.f32x2 %0,%1,%2,%3;" : "=l"(d) : "l"(a), "l"(b), "l"(c)); return d;
}

__device__ __forceinline__ float gelu_exact(float x) {
    return 0.5f * x * (1.0f + erff(x * 0.70710678118654752440f));
}
__device__ __forceinline__ float sigm(float x) {
    return 1.0f / (1.0f + expf(-x));
}

// ---------- scratch (__device__ globals; no allocation allowed) ----------
__device__ __align__(16) float g_enc[BSZ * 6 * HSZ];          // encoded[:, 0:6, :] only
__device__ __align__(16) float g_states[2 * BSZ * HSZ * NSZ]; // SSM states per layer
__device__ __align__(16) float g_gact[BSZ * HSZ];             // gelu(y) GEMM input
__device__ __align__(16) float g_dp[BSZ * HSZ];               // decoder proj (step 0)
__device__ __align__(16) float g_ctx[BSZ * HSZ];
__device__ __align__(16) float g_part[KC * BSZ * HSZ];        // split-K GEMM partials

// ============================================================
// encoded = input_seq @ in_W + in_b  (only s < 6 ever read: ptr in [0,6))
// ============================================================
__global__ void k_enc(const float* __restrict__ inseq,
                      const float* __restrict__ inW,
                      const float* __restrict__ inb) {
    int idx = blockIdx.x * 256 + threadIdx.x;   // < B*6*H
    int h = idx & (HSZ - 1);
    int bs = idx >> 9;                          // b*6 + s
    int b = bs / 6, s = bs - b * 6;
    const float* r = inseq + (b * 64 + s) * 3;
    g_enc[idx] = fmaf(r[0], inW[h],
                 fmaf(r[1], inW[HSZ + h],
                 fmaf(r[2], inW[2 * HSZ + h], inb[h])));
}

// ============================================================
// zero states / ctx
// ============================================================
__global__ void k_init() {
    int idx = blockIdx.x * 256 + threadIdx.x;
    if (idx < 2 * BSZ * HSZ * NSZ) g_states[idx] = 0.0f;
    if (idx < BSZ * HSZ) g_ctx[idx] = 0.0f;
}

// ============================================================
// Step-0 decoder proj + layer-0 SSM (dec0 = [0,0,1], states = 0)
// ============================================================
__global__ void __launch_bounds__(256)
k_first(const float* __restrict__ inW, const float* __restrict__ inb,
        const float* __restrict__ A0, const float* __restrict__ B0,
        const float* __restrict__ C0, const float* __restrict__ D0) {
    int idx = blockIdx.x * 256 + threadIdx.x;   // < B*H
    int h = idx & (HSZ - 1);
    int b = idx >> 9;
    float x = inW[2 * HSZ + h] + inb[h];
    g_dp[idx] = x;

    const float4* B4 = (const float4*)(B0 + h * NSZ);
    const float4* C4 = (const float4*)(C0 + h * NSZ);
    float4* S4p = (float4*)(g_states + ((size_t)b * HSZ + h) * NSZ);
    float acc = 0.0f;
#pragma unroll
    for (int q = 0; q < 4; q++) {
        float4 bm = B4[q], c = C4[q];
        float4 s = make_float4(bm.x * x, bm.y * x, bm.z * x, bm.w * x);
        acc += c.x * s.x + c.y * s.y + c.z * s.z + c.w * s.w;
        S4p[q] = s;
    }
    g_gact[idx] = gelu_exact(fmaf(D0[h], x, acc));
}

// ============================================================
// Split-K GEMM: g_part[kc] = g_gact(256x512) @ W k-chunk kc
// grid (4 ct, 8 rt, 8 kc) = 256 blocks, 256 threads.
// Block tile 32r x 128c x 64k. Thread tile 4r x 4c.
// A pre-duplicated (a,a) in smem -> inner loop is 3x LDS.128 + 8 FFMA2,
// zero pack MOVs. A reads are warp-broadcast; B reads conflict-free.
// ============================================================
#define ADS 34   // Adup row stride in ull (even -> 16B alignment holds)
__global__ void __launch_bounds__(256)
k_gemm(const float* __restrict__ W) {
    __shared__ ull Adup[KCH * ADS];          // [k][row] = (a,a), rows 0..31
    __shared__ float Bs[KCH * 128];          // [k][col]
    int t = threadIdx.x;
    int c0 = blockIdx.x * 128, r0 = blockIdx.y * 32, k0 = blockIdx.z * KCH;

    // stage A: 32 rows x 64 k -> duplicated transpose (2 float4 loads/thread)
    {
        int kk4 = (t & 15) * 4, row = t >> 4;         // row 0..15
#pragma unroll
        for (int p = 0; p < 2; p++) {
            int r = row + 16 * p;
            float4 v = *(const float4*)&g_gact[(r0 + r) * HSZ + k0 + kk4];
            Adup[(kk4 + 0) * ADS + r] = pack2(v.x, v.x);
            Adup[(kk4 + 1) * ADS + r] = pack2(v.y, v.y);
            Adup[(kk4 + 2) * ADS + r] = pack2(v.z, v.z);
            Adup[(kk4 + 3) * ADS + r] = pack2(v.w, v.w);
        }
    }
    // stage B: 64 k x 128 cols (8 float4 copies/thread, coalesced)
    {
#pragma unroll
        for (int i = 0; i < 8; i++) {
            int f = t + i * 256;                      // 0..2047 float4s
            int k = f >> 5, c4 = (f & 31) * 4;
            *(float4*)&Bs[k * 128 + c4] = *(const float4*)&W[(k0 + k) * HSZ + c0 + c4];
        }
    }
    __syncthreads();

    int ty = t >> 5;            // 0..7 : rows r0 + ty*4 .. +4
    int lane = t & 31;          // cols c0 + lane*4 .. +4
    int rbase = ty * 4, cbase = lane * 4;

    ull acc[4][2];
#pragma unroll
    for (int i = 0; i < 4; i++) { acc[i][0] = 0ULL; acc[i][1] = 0ULL; }

#pragma unroll 8
    for (int k = 0; k < KCH; k++) {
        ulonglong2 a01 = *(const ulonglong2*)&Adup[k * ADS + rbase];      // rows 0,1 (dup)
        ulonglong2 a23 = *(const ulonglong2*)&Adup[k * ADS + rbase + 2];  // rows 2,3 (dup)
        ulonglong2 b01 = *(const ulonglong2*)&Bs[k * 128 + cbase];        // cols (0,1),(2,3)
        acc[0][0] = fma2v(a01.x, b01.x, acc[0][0]); acc[0][1] = fma2v(a01.x, b01.y, acc[0][1]);
        acc[1][0] = fma2v(a01.y, b01.x, acc[1][0]); acc[1][1] = fma2v(a01.y, b01.y, acc[1][1]);
        acc[2][0] = fma2v(a23.x, b01.x, acc[2][0]); acc[2][1] = fma2v(a23.x, b01.y, acc[2][1]);
        acc[3][0] = fma2v(a23.y, b01.x, acc[3][0]); acc[3][1] = fma2v(a23.y, b01.y, acc[3][1]);
    }

    float* P = g_part + (size_t)blockIdx.z * BSZ * HSZ;
#pragma unroll
    for (int r = 0; r < 4; r++) {
        float2 v0 = unpack2(acc[r][0]), v1 = unpack2(acc[r][1]);
        *(float4*)&P[(size_t)(r0 + rbase + r) * HSZ + c0 + cbase] =
            make_float4(v0.x, v0.y, v1.x, v1.y);
    }
}

// ============================================================
// ssm1: z0 = sum(partials)+bias (+residual), LN0 -> x, layer-1 SSM -> gact
// 4 batch rows per block (coeffs loaded once, reused 4x). 64 blocks x 512.
// ============================================================
__global__ void __launch_bounds__(512)
k_ssm1(int isstep0,
       const float* __restrict__ ob0, const float* __restrict__ lng0,
       const float* __restrict__ lnb0,
       const float* __restrict__ A1, const float* __restrict__ B1,
       const float* __restrict__ C1, const float* __restrict__ D1) {
    __shared__ float red[4][16], redq[4][16];
    __shared__ float stat[8];
    int b0 = blockIdx.x * 4, t = threadIdx.x;     // t == h
    int lane = t & 31, w = t >> 5;

    float zz[4];
    float bias = ob0[t];
#pragma unroll
    for (int r = 0; r < 4; r++) {
        float y = 0.0f;
#pragma unroll
        for (int z = 0; z < KC; z++)
            y += g_part[((size_t)z * BSZ + b0 + r) * HSZ + t];
        y += bias;
        zz[r] = isstep0 ? (y + g_dp[(b0 + r) * HSZ + t]) : (2.0f * y);
    }

    // per-row LN stats
    {
        float s0 = zz[0], q0 = zz[0] * zz[0], s1 = zz[1], q1 = zz[1] * zz[1];
        float s2 = zz[2], q2 = zz[2] * zz[2], s3 = zz[3], q3 = zz[3] * zz[3];
#pragma unroll
        for (int d = 16; d; d >>= 1) {
            s0 += __shfl_xor_sync(0xFFFFFFFFu, s0, d);
            q0 += __shfl_xor_sync(0xFFFFFFFFu, q0, d);
            s1 += __shfl_xor_sync(0xFFFFFFFFu, s1, d);
            q1 += __shfl_xor_sync(0xFFFFFFFFu, q1, d);
            s2 += __shfl_xor_sync(0xFFFFFFFFu, s2, d);
            q2 += __shfl_xor_sync(0xFFFFFFFFu, q2, d);
            s3 += __shfl_xor_sync(0xFFFFFFFFu, s3, d);
            q3 += __shfl_xor_sync(0xFFFFFFFFu, q3, d);
        }
        if (lane == 0) {
            red[0][w] = s0; redq[0][w] = q0;
            red[1][w] = s1; redq[1][w] = q1;
            red[2][w] = s2; redq[2][w] = q2;
            red[3][w] = s3; redq[3][w] = q3;
        }
    }
    __syncthreads();
    if (t < 4) {
        float ss = 0.0f, qq = 0.0f;
#pragma unroll
        for (int i = 0; i < 16; i++) { ss += red[t][i]; qq += redq[t][i]; }
        float m = ss * (1.0f / HSZ);
        stat[t * 2] = m;
        stat[t * 2 + 1] = rsqrtf(qq * (1.0f / HSZ) - m * m + 1e-5f);
    }
    __syncthreads();

    float g = lng0[t], bbl = lnb0[t];
    float4 ca[4], cb[4], cc[4];
#pragma unroll
    for (int q = 0; q < 4; q++) {
        ca[q] = *(const float4*)(A1 + t * NSZ + q * 4);
        cb[q] = *(const float4*)(B1 + t * NSZ + q * 4);
        cc[q] = *(const float4*)(C1 + t * NSZ + q * 4);
    }
    float dd = D1[t];

#pragma unroll
    for (int r = 0; r < 4; r++) {
        float x = (zz[r] - stat[r * 2]) * stat[r * 2 + 1] * g + bbl;
        float4* sp = (float4*)(g_states + ((size_t)BSZ * HSZ + (size_t)(b0 + r) * HSZ + t) * NSZ);
        float acc = 0.0f;
#pragma unroll
        for (int q = 0; q < 4; q++) {
            float4 s = sp[q];
            s.x = fmaf(ca[q].x, s.x, cb[q].x * x);
            s.y = fmaf(ca[q].y, s.y, cb[q].y * x);
            s.z = fmaf(ca[q].z, s.z, cb[q].z * x);
            s.w = fmaf(ca[q].w, s.w, cb[q].w * x);
            acc += cc[q].x * s.x + cc[q].y * s.y + cc[q].z * s.z + cc[q].w * s.w;
            sp[q] = s;
        }
        g_gact[(b0 + r) * HSZ + t] = gelu_exact(fmaf(dd, x, acc));
    }
}

// ============================================================
// head (+ fused next-step decoder proj & layer-0 SSM)
// 2 batch rows per block, 128 blocks x 512 thr
// ============================================================
__global__ void __launch_bounds__(512)
k_head(int step,
       const float* __restrict__ ob1, const float* __restrict__ lng1,
       const float* __restrict__ lnb1,
       const float* __restrict__ hW, const float* __restrict__ hb,
       const float* __restrict__ inW, const float* __restrict__ inb,
       const float* __restrict__ A0, const float* __restrict__ B0,
       const float* __restrict__ C0, const float* __restrict__ D0,
       float* __restrict__ out) {
    __shared__ float xdc[2][HSZ];
    __shared__ float red[68];
    __shared__ float gv[2][12];
    __shared__ float decs[2][3];
    __shared__ int ptr_s[2];

    int b0 = blockIdx.x * 2, t = threadIdx.x;
    int lane = t & 31, w = t >> 5;

    float y0 = 0.0f, y1 = 0.0f;
    const float* P = g_part + (size_t)b0 * HSZ + t;
#pragma unroll
    for (int z = 0; z < KC; z++) {
        y0 += P[(size_t)z * BSZ * HSZ];
        y1 += P[(size_t)z * BSZ * HSZ + HSZ];
    }
    float bias = ob1[t];
    y0 += bias; y1 += bias;
    float z0, z1;
    if (step == 0) {
        z0 = y0 + g_dp[b0 * HSZ + t];
        z1 = y1 + g_dp[(b0 + 1) * HSZ + t];
    } else { z0 = 2.0f * y0; z1 = 2.0f * y1; }

    float s0 = z0, q0 = z0 * z0, s1 = z1, q1 = z1 * z1;
#pragma unroll
    for (int d = 16; d; d >>= 1) {
        s0 += __shfl_xor_sync(0xFFFFFFFFu, s0, d);
        q0 += __shfl_xor_sync(0xFFFFFFFFu, q0, d);
        s1 += __shfl_xor_sync(0xFFFFFFFFu, s1, d);
        q1 += __shfl_xor_sync(0xFFFFFFFFu, q1, d);
    }
    if (lane == 0) { red[w] = s0; red[16 + w] = q0; red[32 + w] = s1; red[48 + w] = q1; }
    __syncthreads();
    if (t == 0) {
        float a0 = 0, c0s = 0, a1 = 0, c1s = 0;
#pragma unroll
        for (int i = 0; i < 16; i++) { a0 += red[i]; c0s += red[16 + i]; a1 += red[32 + i]; c1s += red[48 + i]; }
        float m0 = a0 * (1.0f / HSZ), m1 = a1 * (1.0f / HSZ);
        red[64] = m0; red[65] = rsqrtf(c0s * (1.0f / HSZ) - m0 * m0 + 1e-5f);
        red[66] = m1; red[67] = rsqrtf(c1s * (1.0f / HSZ) - m1 * m1 + 1e-5f);
    }
    __syncthreads();
    float g = lng1[t], bbl = lnb1[t];
    float xd0 = (z0 - red[64]) * red[65] * g + bbl;
    float xd1 = (z1 - red[66]) * red[67] * g + bbl;
    float ctx0 = g_ctx[b0 * HSZ + t];
    float ctx1 = g_ctx[(b0 + 1) * HSZ + t];
    xdc[0][t] = xd0 + ctx0;
    xdc[1][t] = xd1 + ctx1;
    __syncthreads();

    // head logits for both rows: warp w (<9) computes the two dots
    if (w < ODIM) {
        float a0 = 0.0f, a1 = 0.0f;
#pragma unroll
        for (int q = 0; q < 16; q++) {
            int k = q * 32 + lane;
            float wk = hW[k * ODIM + w];
            a0 = fmaf(xdc[0][k], wk, a0);
            a1 = fmaf(xdc[1][k], wk, a1);
        }
#pragma unroll
        for (int d = 16; d; d >>= 1) {
            a0 += __shfl_xor_sync(0xFFFFFFFFu, a0, d);
            a1 += __shfl_xor_sync(0xFFFFFFFFu, a1, d);
        }
        if (lane == 0) { gv[0][w] = a0 + hb[w]; gv[1][w] = a1 + hb[w]; }
    }
    __syncthreads();

    bool is_out = ((step & 1) == 0);
    if (is_out) {
        if (t < ODIM) out[b0 * (TSTEPS * ODIM) + step * ODIM + t] = sigm(gv[0][t]);
        if (t >= 32 && t < 32 + ODIM)
            out[(b0 + 1) * (TSTEPS * ODIM) + step * ODIM + (t - 32)] = sigm(gv[1][t - 32]);
        if (t < 2) {
            decs[t][0] = (sigm(gv[t][0]) > 0.5f) ? 1.0f : 0.0f;
            decs[t][1] = 1.0f; decs[t][2] = 0.0f;
        }
    } else {
        if (t < 2) {
            float best = sigm(gv[t][3]); int p = 0;
#pragma unroll
            for (int c = 1; c < 6; c++) {
                float v = sigm(gv[t][3 + c]);
                if (v > best) { best = v; p = c; }
            }
            ptr_s[t] = p;
            decs[t][0] = 0.0f; decs[t][1] = 0.0f; decs[t][2] = 1.0f;
        }
        __syncthreads();                       // uniform branch: safe
        const float* ev0 = g_enc + (b0 * 6 + ptr_s[0]) * HSZ;
        const float* ev1 = g_enc + ((b0 + 1) * 6 + ptr_s[1]) * HSZ;
        g_ctx[b0 * HSZ + t] = ctx0 + ev0[t];
        g_ctx[(b0 + 1) * HSZ + t] = ctx1 + ev1[t];
        if (w < ODIM) {
            float a0 = 0.0f, a1 = 0.0f;
#pragma unroll
            for (int q = 0; q < 16; q++) {
                int k = q * 32 + lane;
                float wk = hW[k * ODIM + w];
                a0 = fmaf(ev0[k], wk, a0);
                a1 = fmaf(ev1[k], wk, a1);
            }
#pragma unroll
            for (int d = 16; d; d >>= 1) {
                a0 += __shfl_xor_sync(0xFFFFFFFFu, a0, d);
                a1 += __shfl_xor_sync(0xFFFFFFFFu, a1, d);
            }
            if (lane == 0) {
                out[b0 * (TSTEPS * ODIM) + step * ODIM + w] = sigm(gv[0][w] + a0);
                out[(b0 + 1) * (TSTEPS * ODIM) + step * ODIM + w] = sigm(gv[1][w] + a1);
            }
        }
    }
    __syncthreads();

    // fused next-step: decoder proj + layer-0 SSM for both rows (coeffs once)
    float w0 = inW[t], w1 = inW[HSZ + t], w2 = inW[2 * HSZ + t], ib = inb[t];
    float x0 = fmaf(decs[0][0], w0, fmaf(decs[0][1], w1, fmaf(decs[0][2], w2, ib)));
    float x1 = fmaf(decs[1][0], w0, fmaf(decs[1][1], w1, fmaf(decs[1][2], w2, ib)));

    const float4* A4 = (const float4*)(A0 + t * NSZ);
    const float4* B4 = (const float4*)(B0 + t * NSZ);
    const float4* C4 = (const float4*)(C0 + t * NSZ);
    float4* S0 = (float4*)(g_states + ((size_t)b0 * HSZ + t) * NSZ);
    float4* S1 = S0 + (HSZ * NSZ / 4);
    float acc0 = 0.0f, acc1 = 0.0f;
#pragma unroll
    for (int q = 0; q < 4; q++) {
        float4 a = A4[q], bm = B4[q], c = C4[q];
        float4 s = S0[q];
        s.x = fmaf(a.x, s.x, bm.x * x0); s.y = fmaf(a.y, s.y, bm.y * x0);
        s.z = fmaf(a.z, s.z, bm.z * x0); s.w = fmaf(a.w, s.w, bm.w * x0);
        acc0 += c.x * s.x + c.y * s.y + c.z * s.z + c.w * s.w;
        S0[q] = s;
        s = S1[q];
        s.x = fmaf(a.x, s.x, bm.x * x1); s.y = fmaf(a.y, s.y, bm.y * x1);
        s.z = fmaf(a.z, s.z, bm.z * x1); s.w = fmaf(a.w, s.w, bm.w * x1);
        acc1 += c.x * s.x + c.y * s.y + c.z * s.z + c.w * s.w;
        S1[q] = s;
    }
    float dd = D0[t];
    g_gact[b0 * HSZ + t] = gelu_exact(fmaf(dd, x0, acc0));
    g_gact[(b0 + 1) * HSZ + t] = gelu_exact(fmaf(dd, x1, acc1));
}

// ============================================================
// Launch: 3 setup + 63 x 4 = 255 graph nodes
// ============================================================
extern "C" void kernel_launch(void* const* d_in, const int* in_sizes, int n_in,
                              void* d_out, int out_size) {
    int o = (n_in >= 14) ? 1 : 0;   // skip scalar autoregressive_steps if present
    const float* inseq = (const float*)d_in[0];
    const float* inW = (const float*)d_in[1 + o];
    const float* inb = (const float*)d_in[2 + o];
    const float* A   = (const float*)d_in[3 + o];
    const float* Bm  = (const float*)d_in[4 + o];
    const float* Cm  = (const float*)d_in[5 + o];
    const float* D   = (const float*)d_in[6 + o];
    const float* oW  = (const float*)d_in[7 + o];
    const float* ob  = (const float*)d_in[8 + o];
    const float* lng = (const float*)d_in[9 + o];
    const float* lnb = (const float*)d_in[10 + o];
    const float* hW  = (const float*)d_in[11 + o];
    const float* hb  = (const float*)d_in[12 + o];
    float* out = (float*)d_out;

    const float *A1 = A + HSZ * NSZ, *B1 = Bm + HSZ * NSZ, *C1 = Cm + HSZ * NSZ, *D1 = D + HSZ;
    const float *oW1 = oW + HSZ * HSZ, *ob1 = ob + HSZ;
    const float *lng1 = lng + HSZ, *lnb1 = lnb + HSZ;

    k_enc<<<(BSZ * 6 * HSZ) / 256, 256>>>(inseq, inW, inb);
    k_init<<<(2 * BSZ * HSZ * NSZ) / 256, 256>>>();
    k_first<<<(BSZ * HSZ) / 256, 256>>>(inW, inb, A, Bm, Cm, D);

    dim3 gg(4, 8, KC);   // 4 colblocks x 8 rowblocks x 8 K-chunks = 256 blocks
    for (int i = 0; i < TSTEPS; i++) {
        int s0 = (i == 0) ? 1 : 0;
        k_gemm<<<gg, 256>>>(oW);                                      // layer 0 GEMM
        k_ssm1<<<BSZ / 4, 512>>>(s0, ob, lng, lnb, A1, B1, C1, D1);   // +LN0, layer-1 SSM
        k_gemm<<<gg, 256>>>(oW1);                                     // layer 1 GEMM
        k_head<<<BSZ / 2, 512>>>(i, ob1, lng1, lnb1, hW, hb,
                                 inW, inb, A, Bm, Cm, D, out);        // +LN1, head, next ssm0
    }
}

// round 16
// speedup vs baseline: 1.5869x; 1.0096x over previous
#include <cuda_runtime.h>

#define BSZ 256
#define HSZ 512
#define NSZ 16
#define TSTEPS 63
#define ODIM 9
#define KC 8            // split-K chunks
#define KCH 64          // K per chunk

typedef unsigned long long ull;

// ---------- packed f32x2 helpers (sm_103a FFMA2 path, PTX-only) ----------
__device__ __forceinline__ ull pack2(float lo, float hi) {
    ull r; asm("mov.b64 %0,{%1,%2};" : "=l"(r) : "f"(lo), "f"(hi)); return r;
}
__device__ __forceinline__ float2 unpack2(ull v) {
    float2 r; asm("mov.b64 {%0,%1},%2;" : "=f"(r.x), "=f"(r.y) : "l"(v)); return r;
}
__device__ __forceinline__ ull fma2v(ull a, ull b, ull c) {
    ull d; asm("fma.rn.f32x2 %0,%1,%2,%3;" : "=l"(d) : "l"(a), "l"(b), "l"(c)); return d;
}

__device__ __forceinline__ float gelu_exact(float x) {
    return 0.5f * x * (1.0f + erff(x * 0.70710678118654752440f));
}
__device__ __forceinline__ float sigm(float x) {
    return 1.0f / (1.0f + expf(-x));
}

// ---------- scratch (__device__ globals; no allocation allowed) ----------
__device__ __align__(16) float g_enc[BSZ * 6 * HSZ];          // encoded[:, 0:6, :] only
__device__ __align__(16) float g_states[2 * BSZ * HSZ * NSZ]; // SSM states per layer
__device__ __align__(16) float g_gact[BSZ * HSZ];             // gelu(y) GEMM input
__device__ __align__(16) float g_dp[BSZ * HSZ];               // decoder proj (step 0)
__device__ __align__(16) float g_ctx[BSZ * HSZ];
__device__ __align__(16) float g_part[KC * BSZ * HSZ];        // split-K GEMM partials

// ============================================================
// encoded = input_seq @ in_W + in_b  (only s < 6 ever read: ptr in [0,6))
// ============================================================
__global__ void k_enc(const float* __restrict__ inseq,
                      const float* __restrict__ inW,
                      const float* __restrict__ inb) {
    int idx = blockIdx.x * 256 + threadIdx.x;   // < B*6*H
    int h = idx & (HSZ - 1);
    int bs = idx >> 9;                          // b*6 + s
    int b = bs / 6, s = bs - b * 6;
    const float* r = inseq + (b * 64 + s) * 3;
    g_enc[idx] = fmaf(r[0], inW[h],
                 fmaf(r[1], inW[HSZ + h],
                 fmaf(r[2], inW[2 * HSZ + h], inb[h])));
}

// ============================================================
// zero states / ctx
// ============================================================
__global__ void k_init() {
    int idx = blockIdx.x * 256 + threadIdx.x;
    if (idx < 2 * BSZ * HSZ * NSZ) g_states[idx] = 0.0f;
    if (idx < BSZ * HSZ) g_ctx[idx] = 0.0f;
}

// ============================================================
// Step-0 decoder proj + layer-0 SSM (dec0 = [0,0,1], states = 0)
// ============================================================
__global__ void __launch_bounds__(256)
k_first(const float* __restrict__ inW, const float* __restrict__ inb,
        const float* __restrict__ A0, const float* __restrict__ B0,
        const float* __restrict__ C0, const float* __restrict__ D0) {
    int idx = blockIdx.x * 256 + threadIdx.x;   // < B*H
    int h = idx & (HSZ - 1);
    int b = idx >> 9;
    float x = inW[2 * HSZ + h] + inb[h];
    g_dp[idx] = x;

    const float4* B4 = (const float4*)(B0 + h * NSZ);
    const float4* C4 = (const float4*)(C0 + h * NSZ);
    float4* S4p = (float4*)(g_states + ((size_t)b * HSZ + h) * NSZ);
    float acc = 0.0f;
#pragma unroll
    for (int q = 0; q < 4; q++) {
        float4 bm = B4[q], c = C4[q];
        float4 s = make_float4(bm.x * x, bm.y * x, bm.z * x, bm.w * x);
        acc += c.x * s.x + c.y * s.y + c.z * s.z + c.w * s.w;
        S4p[q] = s;
    }
    g_gact[idx] = gelu_exact(fmaf(D0[h], x, acc));
}

// ============================================================
// Split-K GEMM: g_part[kc] = g_gact(256x512) @ W k-chunk kc
// grid (4 ct, 8 rt, 8 kc) = 256 blocks, 256 threads, 2 blocks/SM.
// Block tile 32r x 128c x 64k. Thread tile 4r x 4c.
// A pre-duplicated (a,a) in smem; inner loop REGISTER-PIPELINED:
// k+1's operands loaded while k's 8 FFMA2 issue -> LDS latency hidden.
// ============================================================
#define ADS 34   // Adup row stride in ull (even -> 16B alignment holds)
__global__ void __launch_bounds__(256, 2)
k_gemm(const float* __restrict__ W) {
    __shared__ ull Adup[KCH * ADS];          // [k][row] = (a,a), rows 0..31
    __shared__ float Bs[KCH * 128];          // [k][col]
    int t = threadIdx.x;
    int c0 = blockIdx.x * 128, r0 = blockIdx.y * 32, k0 = blockIdx.z * KCH;

    // stage A: 32 rows x 64 k -> duplicated transpose (2 float4 loads/thread)
    {
        int kk4 = (t & 15) * 4, row = t >> 4;         // row 0..15
#pragma unroll
        for (int p = 0; p < 2; p++) {
            int r = row + 16 * p;
            float4 v = *(const float4*)&g_gact[(r0 + r) * HSZ + k0 + kk4];
            Adup[(kk4 + 0) * ADS + r] = pack2(v.x, v.x);
            Adup[(kk4 + 1) * ADS + r] = pack2(v.y, v.y);
            Adup[(kk4 + 2) * ADS + r] = pack2(v.z, v.z);
            Adup[(kk4 + 3) * ADS + r] = pack2(v.w, v.w);
        }
    }
    // stage B: 64 k x 128 cols (8 float4 copies/thread, coalesced)
    {
#pragma unroll
        for (int i = 0; i < 8; i++) {
            int f = t + i * 256;                      // 0..2047 float4s
            int k = f >> 5, c4 = (f & 31) * 4;
            *(float4*)&Bs[k * 128 + c4] = *(const float4*)&W[(k0 + k) * HSZ + c0 + c4];
        }
    }
    __syncthreads();

    int ty = t >> 5;            // 0..7 : rows r0 + ty*4 .. +4
    int lane = t & 31;          // cols c0 + lane*4 .. +4
    int rbase = ty * 4, cbase = lane * 4;

    const ull* Ab = &Adup[rbase];            // + k*ADS
    const float* Bb = &Bs[cbase];            // + k*128

    ull acc[4][2];
#pragma unroll
    for (int i = 0; i < 4; i++) { acc[i][0] = 0ULL; acc[i][1] = 0ULL; }

    // software pipeline: prefetch k+1 while computing k
    ulonglong2 a01 = *(const ulonglong2*)(Ab);
    ulonglong2 a23 = *(const ulonglong2*)(Ab + 2);
    ulonglong2 b01 = *(const ulonglong2*)(Bb);

#pragma unroll 8
    for (int k = 0; k < KCH - 1; k++) {
        ulonglong2 a01n = *(const ulonglong2*)(Ab + (k + 1) * ADS);
        ulonglong2 a23n = *(const ulonglong2*)(Ab + (k + 1) * ADS + 2);
        ulonglong2 b01n = *(const ulonglong2*)(Bb + (k + 1) * 128);
        acc[0][0] = fma2v(a01.x, b01.x, acc[0][0]); acc[0][1] = fma2v(a01.x, b01.y, acc[0][1]);
        acc[1][0] = fma2v(a01.y, b01.x, acc[1][0]); acc[1][1] = fma2v(a01.y, b01.y, acc[1][1]);
        acc[2][0] = fma2v(a23.x, b01.x, acc[2][0]); acc[2][1] = fma2v(a23.x, b01.y, acc[2][1]);
        acc[3][0] = fma2v(a23.y, b01.x, acc[3][0]); acc[3][1] = fma2v(a23.y, b01.y, acc[3][1]);
        a01 = a01n; a23 = a23n; b01 = b01n;
    }
    // last iteration
    acc[0][0] = fma2v(a01.x, b01.x, acc[0][0]); acc[0][1] = fma2v(a01.x, b01.y, acc[0][1]);
    acc[1][0] = fma2v(a01.y, b01.x, acc[1][0]); acc[1][1] = fma2v(a01.y, b01.y, acc[1][1]);
    acc[2][0] = fma2v(a23.x, b01.x, acc[2][0]); acc[2][1] = fma2v(a23.x, b01.y, acc[2][1]);
    acc[3][0] = fma2v(a23.y, b01.x, acc[3][0]); acc[3][1] = fma2v(a23.y, b01.y, acc[3][1]);

    float* P = g_part + (size_t)blockIdx.z * BSZ * HSZ;
#pragma unroll
    for (int r = 0; r < 4; r++) {
        float2 v0 = unpack2(acc[r][0]), v1 = unpack2(acc[r][1]);
        *(float4*)&P[(size_t)(r0 + rbase + r) * HSZ + c0 + cbase] =
            make_float4(v0.x, v0.y, v1.x, v1.y);
    }
}

// ============================================================
// ssm1: z0 = sum(partials)+bias (+residual), LN0 -> x, layer-1 SSM -> gact
// 4 batch rows per block (coeffs loaded once, reused 4x). 64 blocks x 512.
// ============================================================
__global__ void __launch_bounds__(512)
k_ssm1(int isstep0,
       const float* __restrict__ ob0, const float* __restrict__ lng0,
       const float* __restrict__ lnb0,
       const float* __restrict__ A1, const float* __restrict__ B1,
       const float* __restrict__ C1, const float* __restrict__ D1) {
    __shared__ float red[4][16], redq[4][16];
    __shared__ float stat[8];
    int b0 = blockIdx.x * 4, t = threadIdx.x;     // t == h
    int lane = t & 31, w = t >> 5;

    float zz[4];
    float bias = ob0[t];
#pragma unroll
    for (int r = 0; r < 4; r++) {
        float y = 0.0f;
#pragma unroll
        for (int z = 0; z < KC; z++)
            y += g_part[((size_t)z * BSZ + b0 + r) * HSZ + t];
        y += bias;
        zz[r] = isstep0 ? (y + g_dp[(b0 + r) * HSZ + t]) : (2.0f * y);
    }

    // per-row LN stats
    {
        float s0 = zz[0], q0 = zz[0] * zz[0], s1 = zz[1], q1 = zz[1] * zz[1];
        float s2 = zz[2], q2 = zz[2] * zz[2], s3 = zz[3], q3 = zz[3] * zz[3];
#pragma unroll
        for (int d = 16; d; d >>= 1) {
            s0 += __shfl_xor_sync(0xFFFFFFFFu, s0, d);
            q0 += __shfl_xor_sync(0xFFFFFFFFu, q0, d);
            s1 += __shfl_xor_sync(0xFFFFFFFFu, s1, d);
            q1 += __shfl_xor_sync(0xFFFFFFFFu, q1, d);
            s2 += __shfl_xor_sync(0xFFFFFFFFu, s2, d);
            q2 += __shfl_xor_sync(0xFFFFFFFFu, q2, d);
            s3 += __shfl_xor_sync(0xFFFFFFFFu, s3, d);
            q3 += __shfl_xor_sync(0xFFFFFFFFu, q3, d);
        }
        if (lane == 0) {
            red[0][w] = s0; redq[0][w] = q0;
            red[1][w] = s1; redq[1][w] = q1;
            red[2][w] = s2; redq[2][w] = q2;
            red[3][w] = s3; redq[3][w] = q3;
        }
    }
    __syncthreads();
    if (t < 4) {
        float ss = 0.0f, qq = 0.0f;
#pragma unroll
        for (int i = 0; i < 16; i++) { ss += red[t][i]; qq += redq[t][i]; }
        float m = ss * (1.0f / HSZ);
        stat[t * 2] = m;
        stat[t * 2 + 1] = rsqrtf(qq * (1.0f / HSZ) - m * m + 1e-5f);
    }
    __syncthreads();

    float g = lng0[t], bbl = lnb0[t];
    float4 ca[4], cb[4], cc[4];
#pragma unroll
    for (int q = 0; q < 4; q++) {
        ca[q] = *(const float4*)(A1 + t * NSZ + q * 4);
        cb[q] = *(const float4*)(B1 + t * NSZ + q * 4);
        cc[q] = *(const float4*)(C1 + t * NSZ + q * 4);
    }
    float dd = D1[t];

#pragma unroll
    for (int r = 0; r < 4; r++) {
        float x = (zz[r] - stat[r * 2]) * stat[r * 2 + 1] * g + bbl;
        float4* sp = (float4*)(g_states + ((size_t)BSZ * HSZ + (size_t)(b0 + r) * HSZ + t) * NSZ);
        float acc = 0.0f;
#pragma unroll
        for (int q = 0; q < 4; q++) {
            float4 s = sp[q];
            s.x = fmaf(ca[q].x, s.x, cb[q].x * x);
            s.y = fmaf(ca[q].y, s.y, cb[q].y * x);
            s.z = fmaf(ca[q].z, s.z, cb[q].z * x);
            s.w = fmaf(ca[q].w, s.w, cb[q].w * x);
            acc += cc[q].x * s.x + cc[q].y * s.y + cc[q].z * s.z + cc[q].w * s.w;
            sp[q] = s;
        }
        g_gact[(b0 + r) * HSZ + t] = gelu_exact(fmaf(dd, x, acc));
    }
}

// ============================================================
// head (+ fused next-step decoder proj & layer-0 SSM)
// 2 batch rows per block, 128 blocks x 512 thr
// ============================================================
__global__ void __launch_bounds__(512)
k_head(int step,
       const float* __restrict__ ob1, const float* __restrict__ lng1,
       const float* __restrict__ lnb1,
       const float* __restrict__ hW, const float* __restrict__ hb,
       const float* __restrict__ inW, const float* __restrict__ inb,
       const float* __restrict__ A0, const float* __restrict__ B0,
       const float* __restrict__ C0, const float* __restrict__ D0,
       float* __restrict__ out) {
    __shared__ float xdc[2][HSZ];
    __shared__ float red[68];
    __shared__ float gv[2][12];
    __shared__ float decs[2][3];
    __shared__ int ptr_s[2];

    int b0 = blockIdx.x * 2, t = threadIdx.x;
    int lane = t & 31, w = t >> 5;

    float y0 = 0.0f, y1 = 0.0f;
    const float* P = g_part + (size_t)b0 * HSZ + t;
#pragma unroll
    for (int z = 0; z < KC; z++) {
        y0 += P[(size_t)z * BSZ * HSZ];
        y1 += P[(size_t)z * BSZ * HSZ + HSZ];
    }
    float bias = ob1[t];
    y0 += bias; y1 += bias;
    float z0, z1;
    if (step == 0) {
        z0 = y0 + g_dp[b0 * HSZ + t];
        z1 = y1 + g_dp[(b0 + 1) * HSZ + t];
    } else { z0 = 2.0f * y0; z1 = 2.0f * y1; }

    float s0 = z0, q0 = z0 * z0, s1 = z1, q1 = z1 * z1;
#pragma unroll
    for (int d = 16; d; d >>= 1) {
        s0 += __shfl_xor_sync(0xFFFFFFFFu, s0, d);
        q0 += __shfl_xor_sync(0xFFFFFFFFu, q0, d);
        s1 += __shfl_xor_sync(0xFFFFFFFFu, s1, d);
        q1 += __shfl_xor_sync(0xFFFFFFFFu, q1, d);
    }
    if (lane == 0) { red[w] = s0; red[16 + w] = q0; red[32 + w] = s1; red[48 + w] = q1; }
    __syncthreads();
    if (t == 0) {
        float a0 = 0, c0s = 0, a1 = 0, c1s = 0;
#pragma unroll
        for (int i = 0; i < 16; i++) { a0 += red[i]; c0s += red[16 + i]; a1 += red[32 + i]; c1s += red[48 + i]; }
        float m0 = a0 * (1.0f / HSZ), m1 = a1 * (1.0f / HSZ);
        red[64] = m0; red[65] = rsqrtf(c0s * (1.0f / HSZ) - m0 * m0 + 1e-5f);
        red[66] = m1; red[67] = rsqrtf(c1s * (1.0f / HSZ) - m1 * m1 + 1e-5f);
    }
    __syncthreads();
    float g = lng1[t], bbl = lnb1[t];
    float xd0 = (z0 - red[64]) * red[65] * g + bbl;
    float xd1 = (z1 - red[66]) * red[67] * g + bbl;
    float ctx0 = g_ctx[b0 * HSZ + t];
    float ctx1 = g_ctx[(b0 + 1) * HSZ + t];
    xdc[0][t] = xd0 + ctx0;
    xdc[1][t] = xd1 + ctx1;
    __syncthreads();

    // head logits for both rows: warp w (<9) computes the two dots
    if (w < ODIM) {
        float a0 = 0.0f, a1 = 0.0f;
#pragma unroll
        for (int q = 0; q < 16; q++) {
            int k = q * 32 + lane;
            float wk = hW[k * ODIM + w];
            a0 = fmaf(xdc[0][k], wk, a0);
            a1 = fmaf(xdc[1][k], wk, a1);
        }
#pragma unroll
        for (int d = 16; d; d >>= 1) {
            a0 += __shfl_xor_sync(0xFFFFFFFFu, a0, d);
            a1 += __shfl_xor_sync(0xFFFFFFFFu, a1, d);
        }
        if (lane == 0) { gv[0][w] = a0 + hb[w]; gv[1][w] = a1 + hb[w]; }
    }
    __syncthreads();

    bool is_out = ((step & 1) == 0);
    if (is_out) {
        if (t < ODIM) out[b0 * (TSTEPS * ODIM) + step * ODIM + t] = sigm(gv[0][t]);
        if (t >= 32 && t < 32 + ODIM)
            out[(b0 + 1) * (TSTEPS * ODIM) + step * ODIM + (t - 32)] = sigm(gv[1][t - 32]);
        if (t < 2) {
            decs[t][0] = (sigm(gv[t][0]) > 0.5f) ? 1.0f : 0.0f;
            decs[t][1] = 1.0f; decs[t][2] = 0.0f;
        }
    } else {
        if (t < 2) {
            float best = sigm(gv[t][3]); int p = 0;
#pragma unroll
            for (int c = 1; c < 6; c++) {
                float v = sigm(gv[t][3 + c]);
                if (v > best) { best = v; p = c; }
            }
            ptr_s[t] = p;
            decs[t][0] = 0.0f; decs[t][1] = 0.0f; decs[t][2] = 1.0f;
        }
        __syncthreads();                       // uniform branch: safe
        const float* ev0 = g_enc + (b0 * 6 + ptr_s[0]) * HSZ;
        const float* ev1 = g_enc + ((b0 + 1) * 6 + ptr_s[1]) * HSZ;
        g_ctx[b0 * HSZ + t] = ctx0 + ev0[t];
        g_ctx[(b0 + 1) * HSZ + t] = ctx1 + ev1[t];
        if (w < ODIM) {
            float a0 = 0.0f, a1 = 0.0f;
#pragma unroll
            for (int q = 0; q < 16; q++) {
                int k = q * 32 + lane;
                float wk = hW[k * ODIM + w];
                a0 = fmaf(ev0[k], wk, a0);
                a1 = fmaf(ev1[k], wk, a1);
            }
#pragma unroll
            for (int d = 16; d; d >>= 1) {
                a0 += __shfl_xor_sync(0xFFFFFFFFu, a0, d);
                a1 += __shfl_xor_sync(0xFFFFFFFFu, a1, d);
            }
            if (lane == 0) {
                out[b0 * (TSTEPS * ODIM) + step * ODIM + w] = sigm(gv[0][w] + a0);
                out[(b0 + 1) * (TSTEPS * ODIM) + step * ODIM + w] = sigm(gv[1][w] + a1);
            }
        }
    }
    __syncthreads();

    // fused next-step: decoder proj + layer-0 SSM for both rows (coeffs once)
    float w0 = inW[t], w1 = inW[HSZ + t], w2 = inW[2 * HSZ + t], ib = inb[t];
    float x0 = fmaf(decs[0][0], w0, fmaf(decs[0][1], w1, fmaf(decs[0][2], w2, ib)));
    float x1 = fmaf(decs[1][0], w0, fmaf(decs[1][1], w1, fmaf(decs[1][2], w2, ib)));

    const float4* A4 = (const float4*)(A0 + t * NSZ);
    const float4* B4 = (const float4*)(B0 + t * NSZ);
    const float4* C4 = (const float4*)(C0 + t * NSZ);
    float4* S0 = (float4*)(g_states + ((size_t)b0 * HSZ + t) * NSZ);
    float4* S1 = S0 + (HSZ * NSZ / 4);
    float acc0 = 0.0f, acc1 = 0.0f;
#pragma unroll
    for (int q = 0; q < 4; q++) {
        float4 a = A4[q], bm = B4[q], c = C4[q];
        float4 s = S0[q];
        s.x = fmaf(a.x, s.x, bm.x * x0); s.y = fmaf(a.y, s.y, bm.y * x0);
        s.z = fmaf(a.z, s.z, bm.z * x0); s.w = fmaf(a.w, s.w, bm.w * x0);
        acc0 += c.x * s.x + c.y * s.y + c.z * s.z + c.w * s.w;
        S0[q] = s;
        s = S1[q];
        s.x = fmaf(a.x, s.x, bm.x * x1); s.y = fmaf(a.y, s.y, bm.y * x1);
        s.z = fmaf(a.z, s.z, bm.z * x1); s.w = fmaf(a.w, s.w, bm.w * x1);
        acc1 += c.x * s.x + c.y * s.y + c.z * s.z + c.w * s.w;
        S1[q] = s;
    }
    float dd = D0[t];
    g_gact[b0 * HSZ + t] = gelu_exact(fmaf(dd, x0, acc0));
    g_gact[(b0 + 1) * HSZ + t] = gelu_exact(fmaf(dd, x1, acc1));
}

// ============================================================
// Launch: 3 setup + 63 x 4 = 255 graph nodes
// ============================================================
extern "C" void kernel_launch(void* const* d_in, const int* in_sizes, int n_in,
                              void* d_out, int out_size) {
    int o = (n_in >= 14) ? 1 : 0;   // skip scalar autoregressive_steps if present
    const float* inseq = (const float*)d_in[0];
    const float* inW = (const float*)d_in[1 + o];
    const float* inb = (const float*)d_in[2 + o];
    const float* A   = (const float*)d_in[3 + o];
    const float* Bm  = (const float*)d_in[4 + o];
    const float* Cm  = (const float*)d_in[5 + o];
    const float* D   = (const float*)d_in[6 + o];
    const float* oW  = (const float*)d_in[7 + o];
    const float* ob  = (const float*)d_in[8 + o];
    const float* lng = (const float*)d_in[9 + o];
    const float* lnb = (const float*)d_in[10 + o];
    const float* hW  = (const float*)d_in[11 + o];
    const float* hb  = (const float*)d_in[12 + o];
    float* out = (float*)d_out;

    const float *A1 = A + HSZ * NSZ, *B1 = Bm + HSZ * NSZ, *C1 = Cm + HSZ * NSZ, *D1 = D + HSZ;
    const float *oW1 = oW + HSZ * HSZ, *ob1 = ob + HSZ;
    const float *lng1 = lng + HSZ, *lnb1 = lnb + HSZ;

    k_enc<<<(BSZ * 6 * HSZ) / 256, 256>>>(inseq, inW, inb);
    k_init<<<(2 * BSZ * HSZ * NSZ) / 256, 256>>>();
    k_first<<<(BSZ * HSZ) / 256, 256>>>(inW, inb, A, Bm, Cm, D);

    dim3 gg(4, 8, KC);   // 4 colblocks x 8 rowblocks x 8 K-chunks = 256 blocks
    for (int i = 0; i < TSTEPS; i++) {
        int s0 = (i == 0) ? 1 : 0;
        k_gemm<<<gg, 256>>>(oW);                                      // layer 0 GEMM
        k_ssm1<<<BSZ / 4, 512>>>(s0, ob, lng, lnb, A1, B1, C1, D1);   // +LN0, layer-1 SSM
        k_gemm<<<gg, 256>>>(oW1);                                     // layer 1 GEMM
        k_head<<<BSZ / 2, 512>>>(i, ob1, lng1, lnb1, hW, hb,
                                 inW, inb, A, Bm, Cm, D, out);        // +LN1, head, next ssm0
    }
}